// round 14
// baseline (speedup 1.0000x reference)
#include <cuda_runtime.h>
#include <cuda_bf16.h>

typedef unsigned long long ull;
typedef unsigned int u32;

#define PIXN 50176
#define KDIM 384

// ---------------- scratch (static device allocations) ----------------
__device__ float g_qkv[57802752];                 // [PIXN][1152] f32, window-major rows, head-major channels
__device__ __nv_bfloat16 g_xh[19267584];          // x bf16 hi, window-major rows (rolled)
__device__ __nv_bfloat16 g_xl[19267584];
__device__ __nv_bfloat16 g_ah[19267584];          // attention out hi, window-major rows
__device__ __nv_bfloat16 g_al[19267584];
__device__ __nv_bfloat16 g_wqh[442368];           // w_qkv bf16 hi, rows permuted to h*96+mat*32+d
__device__ __nv_bfloat16 g_wql[442368];
__device__ __nv_bfloat16 g_woh[147456];
__device__ __nv_bfloat16 g_wol[147456];

// ---------------- helpers ----------------
__device__ __forceinline__ int roll3(int m) {
    int b = m / 3136; int p = m - b * 3136;
    int i = p / 56;   int j = p - i * 56;
    i += 3; if (i >= 56) i -= 56;
    j += 3; if (j >= 56) j -= 56;
    return b * 3136 + i * 56 + j;
}
// window-major index -> pixel index (same batch)
__device__ __forceinline__ int winpix(int m) {
    int b = m / 3136; int r = m - b * 3136;
    int win = r / 49;  int tok = r - win * 49;
    int wi = win >> 3, wj = win & 7;
    int ti = tok / 7,  tj = tok - ti * 7;
    return b * 3136 + (wi * 7 + ti) * 56 + wj * 7 + tj;
}

__device__ __forceinline__ ull fpack(float x, float y) {
    ull r; asm("mov.b64 %0, {%1, %2};" : "=l"(r) : "f"(x), "f"(y)); return r;
}
__device__ __forceinline__ void ffma2(ull &c, ull a, ull b) {
    asm("fma.rn.f32x2 %0, %1, %2, %0;" : "+l"(c) : "l"(a), "l"(b));
}
__device__ __forceinline__ float2 funpack(ull v) {
    float2 r; asm("mov.b64 {%0, %1}, %2;" : "=f"(r.x), "=f"(r.y) : "l"(v)); return r;
}
__device__ __forceinline__ u32 s2u(const void* p) {
    u32 a; asm("{ .reg .u64 t; cvta.to.shared.u64 t, %1; cvt.u32.u64 %0, t; }" : "=r"(a) : "l"(p));
    return a;
}
__device__ __forceinline__ void bsplit(float v, __nv_bfloat16& h, __nv_bfloat16& l) {
    h = __float2bfloat16(v);
    l = __float2bfloat16(v - __bfloat162float(h));
}
__device__ __forceinline__ ull pack4bf(__nv_bfloat16 a, __nv_bfloat16 b,
                                       __nv_bfloat16 c, __nv_bfloat16 d) {
    union { ull u; __nv_bfloat162 v[2]; } t;
    t.v[0] = __nv_bfloat162{a, b};
    t.v[1] = __nv_bfloat162{c, d};
    return t.u;
}
__device__ __forceinline__ void cp_async16(u32 d, const void* g) {
    asm volatile("cp.async.cg.shared.global [%0], [%1], 16;" :: "r"(d), "l"(g) : "memory");
}
__device__ __forceinline__ void ldsm4(u32* r, u32 addr) {
    asm volatile("ldmatrix.sync.aligned.m8n8.x4.shared.b16 {%0,%1,%2,%3}, [%4];"
                 : "=r"(r[0]), "=r"(r[1]), "=r"(r[2]), "=r"(r[3]) : "r"(addr));
}
__device__ __forceinline__ void mma_bf16(float* c, const u32* a, const u32* b) {
    asm volatile("mma.sync.aligned.m16n8k16.row.col.f32.bf16.bf16.f32 "
                 "{%0,%1,%2,%3},{%4,%5,%6,%7},{%8,%9},{%0,%1,%2,%3};"
                 : "+f"(c[0]), "+f"(c[1]), "+f"(c[2]), "+f"(c[3])
                 : "r"(a[0]), "r"(a[1]), "r"(a[2]), "r"(a[3]), "r"(b[0]), "r"(b[1]));
}

// XOR-swizzled 64B-row address (same scheme as GEMM smem)
__device__ __forceinline__ u32 sw_addr(u32 base, int row, int kc) {
    return base + row * 64 + ((((u32)kc >> 3) ^ (((u32)row >> 1) & 3)) << 4);
}

// ---------------- conversion kernels ----------------
__global__ void conv_roll_kernel(const float* __restrict__ x,
                                 __nv_bfloat16* __restrict__ hi,
                                 __nv_bfloat16* __restrict__ lo)
{
    int idx = blockIdx.x * 256 + threadIdx.x;       // over float4, PIXN*96 total
    if (idx >= PIXN * 96) return;
    int m = idx / 96, j = idx - m * 96;             // m = window-major dst row
    int src = roll3(winpix(m));
    float4 v = ((const float4*)x)[(size_t)src * 96 + j];
    __nv_bfloat16 h0, h1, h2, h3, l0, l1, l2, l3;
    bsplit(v.x, h0, l0); bsplit(v.y, h1, l1); bsplit(v.z, h2, l2); bsplit(v.w, h3, l3);
    __nv_bfloat162* hp = (__nv_bfloat162*)(hi + (size_t)m * 384 + j * 4);
    __nv_bfloat162* lp = (__nv_bfloat162*)(lo + (size_t)m * 384 + j * 4);
    hp[0] = __nv_bfloat162{h0, h1}; hp[1] = __nv_bfloat162{h2, h3};
    lp[0] = __nv_bfloat162{l0, l1}; lp[1] = __nv_bfloat162{l2, l3};
}

// w_qkv with row permutation: dst row c' = h*96 + mat*32 + d  <-  src row mat*384 + h*32 + d
__global__ void conv_wqkv_kernel(const float* __restrict__ a,
                                 __nv_bfloat16* __restrict__ hi,
                                 __nv_bfloat16* __restrict__ lo)
{
    int idx = blockIdx.x * 256 + threadIdx.x;       // over float4, 1152*96 total
    if (idx >= 110592) return;
    int drow = idx / 96, j = idx - drow * 96;
    int h = drow / 96, rem = drow - h * 96;
    int mat = rem >> 5, d = rem & 31;
    int srow = mat * 384 + h * 32 + d;
    float4 v = ((const float4*)a)[(size_t)srow * 96 + j];
    __nv_bfloat16 h0, h1, h2, h3, l0, l1, l2, l3;
    bsplit(v.x, h0, l0); bsplit(v.y, h1, l1); bsplit(v.z, h2, l2); bsplit(v.w, h3, l3);
    __nv_bfloat162* hp = (__nv_bfloat162*)(hi + (size_t)drow * 384 + j * 4);
    __nv_bfloat162* lp = (__nv_bfloat162*)(lo + (size_t)drow * 384 + j * 4);
    hp[0] = __nv_bfloat162{h0, h1}; hp[1] = __nv_bfloat162{h2, h3};
    lp[0] = __nv_bfloat162{l0, l1}; lp[1] = __nv_bfloat162{l2, l3};
}

__global__ void conv_plain_kernel(const float* __restrict__ a,
                                  __nv_bfloat16* __restrict__ hi,
                                  __nv_bfloat16* __restrict__ lo, int n4)
{
    int idx = blockIdx.x * 256 + threadIdx.x;
    if (idx >= n4) return;
    float4 v = ((const float4*)a)[idx];
    __nv_bfloat16 h0, h1, h2, h3, l0, l1, l2, l3;
    bsplit(v.x, h0, l0); bsplit(v.y, h1, l1); bsplit(v.z, h2, l2); bsplit(v.w, h3, l3);
    __nv_bfloat162* hp = (__nv_bfloat162*)(hi + (size_t)idx * 4);
    __nv_bfloat162* lp = (__nv_bfloat162*)(lo + (size_t)idx * 4);
    hp[0] = __nv_bfloat162{h0, h1}; hp[1] = __nv_bfloat162{h2, h3};
    lp[0] = __nv_bfloat162{l0, l1}; lp[1] = __nv_bfloat162{l2, l3};
}

// ---------------- warp-MMA split-bf16 GEMM (R12 structure, committed) ----------------
#define MATB_A 8192            // 128 rows * 64B
#define MATB_B 4096            // 64 rows * 64B
#define STAGE  24576           // Ah, Al, Bh, Bl
#define NSTG   3
#define GEMM_SMEM (NSTG * STAGE)
#define NCHUNK 12

template<bool BIAS, bool ROLLOUT>
__global__ __launch_bounds__(128, 3)
void gemm_mma(const __nv_bfloat16* __restrict__ Ah, const __nv_bfloat16* __restrict__ Al,
              const __nv_bfloat16* __restrict__ Bh, const __nv_bfloat16* __restrict__ Bl,
              const float* __restrict__ bias, float* __restrict__ C, int N)
{
    extern __shared__ char smem[];
    const int tid = threadIdx.x;
    const int wid = tid >> 5, lane = tid & 31;
    const int mBase = blockIdx.y * 128, nBase = blockIdx.x * 64;
    const int wm = wid;

    const u32 s0 = s2u(smem);
    const char* Ahc = (const char*)Ah;
    const char* Alc = (const char*)Al;
    const char* Bhc = (const char*)Bh;
    const char* Blc = (const char*)Bl;

    float c[2][8][4];
#pragma unroll
    for (int i = 0; i < 2; i++)
#pragma unroll
        for (int j = 0; j < 8; j++)
#pragma unroll
            for (int k = 0; k < 4; k++) c[i][j][k] = 0.f;

    const int lmat = lane >> 3;
    const int arow0 = wm * 32 + ((lmat & 1) ? 8 : 0) + (lane & 7);
    const int akc0  = (lmat & 2) ? 8 : 0;
    const int brow0 = ((lmat & 2) ? 8 : 0) + (lane & 7);
    const int bkc0  = (lmat & 1) ? 8 : 0;

    auto load_chunk = [&](int ck, int st) {
        u32 sbase = s0 + st * STAGE;
#pragma unroll
        for (int v = 0; v < 12; v++) {
            int idx = v * 128 + tid;          // 0..1535
            const char* g;
            u32 dst;
            if (idx < 1024) {
                int mat = idx >> 9;
                int r   = (idx >> 2) & 127;
                int cc  = idx & 3;
                const char* gb = (mat == 0) ? Ahc : Alc;
                g = gb + (size_t)(mBase + r) * 768 + ck * 64 + cc * 16;
                u32 swg = (u32)cc ^ (((u32)r >> 1) & 3);
                dst = sbase + mat * MATB_A + r * 64 + swg * 16;
            } else {
                int j   = idx - 1024;
                int mat = j >> 8;
                int r   = (j >> 2) & 63;
                int cc  = j & 3;
                const char* gb = (mat == 0) ? Bhc : Blc;
                g = gb + (size_t)(nBase + r) * 768 + ck * 64 + cc * 16;
                u32 swg = (u32)cc ^ (((u32)r >> 1) & 3);
                dst = sbase + 2 * MATB_A + mat * MATB_B + r * 64 + swg * 16;
            }
            cp_async16(dst, g);
        }
        asm volatile("cp.async.commit_group;" ::: "memory");
    };

    auto compute = [&](int st) {
        u32 sbase = s0 + st * STAGE;
        const u32 bhb = sbase + 2 * MATB_A;
        const u32 blb = bhb + MATB_B;
#pragma unroll
        for (int ks = 0; ks < 2; ks++) {
            const int kb = ks * 16;
            u32 ah[2][4], al[2][4], bh[4][4];
            ldsm4(ah[0], sw_addr(sbase,          arow0,      kb + akc0));
            ldsm4(ah[1], sw_addr(sbase,          arow0 + 16, kb + akc0));
            ldsm4(al[0], sw_addr(sbase + MATB_A, arow0,      kb + akc0));
            ldsm4(al[1], sw_addr(sbase + MATB_A, arow0 + 16, kb + akc0));
#pragma unroll
            for (int p = 0; p < 4; p++)
                ldsm4(bh[p], sw_addr(bhb, brow0 + p * 16, kb + bkc0));
#pragma unroll
            for (int p = 0; p < 4; p++) {
                mma_bf16(c[0][2 * p],     ah[0], bh[p]);
                mma_bf16(c[1][2 * p],     ah[1], bh[p]);
                mma_bf16(c[0][2 * p + 1], ah[0], bh[p] + 2);
                mma_bf16(c[1][2 * p + 1], ah[1], bh[p] + 2);
            }
#pragma unroll
            for (int p = 0; p < 4; p++) {
                mma_bf16(c[0][2 * p],     al[0], bh[p]);
                mma_bf16(c[1][2 * p],     al[1], bh[p]);
                mma_bf16(c[0][2 * p + 1], al[0], bh[p] + 2);
                mma_bf16(c[1][2 * p + 1], al[1], bh[p] + 2);
            }
#pragma unroll
            for (int p = 0; p < 4; p++) {
                u32 u[4];
                ldsm4(u, sw_addr(blb, brow0 + p * 16, kb + bkc0));
                mma_bf16(c[0][2 * p],     ah[0], u);
                mma_bf16(c[1][2 * p],     ah[1], u);
                mma_bf16(c[0][2 * p + 1], ah[0], u + 2);
                mma_bf16(c[1][2 * p + 1], ah[1], u + 2);
            }
        }
    };

    load_chunk(0, 0);
    load_chunk(1, 1);
    int st = 0, pst = 2;
#pragma unroll 1
    for (int ck = 0; ck < NCHUNK; ck++) {
        if (ck < NCHUNK - 1)
            asm volatile("cp.async.wait_group 1;" ::: "memory");
        else
            asm volatile("cp.async.wait_group 0;" ::: "memory");
        __syncthreads();
        if (ck < NCHUNK - 2) load_chunk(ck + 2, pst);
        compute(st);
        st = (st == NSTG - 1) ? 0 : st + 1;
        pst = (pst == NSTG - 1) ? 0 : pst + 1;
    }

#pragma unroll
    for (int mt = 0; mt < 2; mt++) {
#pragma unroll
        for (int half = 0; half < 2; half++) {
            int row = mBase + wm * 32 + mt * 16 + (lane >> 2) + half * 8;
            if (ROLLOUT) row = roll3(winpix(row));   // window-major -> unrolled pixel
            float* cp = C + (size_t)row * N + nBase + (lane & 3) * 2;
#pragma unroll
            for (int nt = 0; nt < 8; nt++) {
                float2 v;
                v.x = c[mt][nt][half * 2 + 0];
                v.y = c[mt][nt][half * 2 + 1];
                if (BIAS) {
                    int col = nBase + nt * 8 + (lane & 3) * 2;
                    v.x += bias[col]; v.y += bias[col + 1];
                }
                *(float2*)(cp + nt * 8) = v;
            }
        }
    }
}

// ---------------- windowed attention: HMMA scores, compact smem ----------------
// 12288 blocks x 128 threads (R6 structure). Scores on tensor cores via
// split-bf16 3-pass; q/k tiles in XOR-swizzled 64B rows (16KB total);
// sc 49x56 (rows >=49 guarded out in the MMA epilogue). ~35KB smem -> 6 blocks/SM.
#define SC 56

__global__ __launch_bounds__(128, 6)
void attn_kernel(const float* __restrict__ rel, const float* __restrict__ qkv,
                 __nv_bfloat16* __restrict__ oh, __nv_bfloat16* __restrict__ ol)
{
    const int h   = blockIdx.x;
    const int win = blockIdx.y;
    const int b   = blockIdx.z;
    const int tid = threadIdx.x;
    const int warp = tid >> 5, lane = tid & 31;

    __shared__ __nv_bfloat16 qh[64 * 32];   // 4KB each, 64B swizzled rows
    __shared__ __nv_bfloat16 ql[64 * 32];
    __shared__ __nv_bfloat16 kh[64 * 32];
    __shared__ __nv_bfloat16 kl[64 * 32];
    __shared__ float vs[49 * 36];
    __shared__ float sc[49 * SC];
    __shared__ float rel_s[169];

    const bool masked = (win >= 56);   // wi == 7

    for (int i = tid; i < 169; i += 128) rel_s[i] = rel[i * 12 + h];

    // ---- streaming gather: q/k split-bf16 into swizzled tiles, v f32 ----
    const int rowbase = b * 3136 + win * 49;
    const float* pb = qkv + (size_t)rowbase * 1152 + h * 96;
    char* qh_c = (char*)qh; char* ql_c = (char*)ql;
    char* kh_c = (char*)kh; char* kl_c = (char*)kl;
    for (int idx = tid; idx < 49 * 8; idx += 128) {
        int tok = idx >> 3, d4 = idx & 7;
        const float* p = pb + (size_t)tok * 1152 + d4 * 4;
        float4 qv = *(const float4*)(p);
        float4 kv = *(const float4*)(p + 32);
        float4 vv = *(const float4*)(p + 64);
        *(float4*)&vs[tok * 36 + d4 * 4] = vv;
        u32 off = (u32)tok * 64 + (((u32)(d4 >> 1) ^ (((u32)tok >> 1) & 3)) << 4)
                + (u32)(d4 & 1) * 8;
        __nv_bfloat16 h0, h1, h2, h3, l0, l1, l2, l3;
        bsplit(qv.x, h0, l0); bsplit(qv.y, h1, l1);
        bsplit(qv.z, h2, l2); bsplit(qv.w, h3, l3);
        *(ull*)(qh_c + off) = pack4bf(h0, h1, h2, h3);
        *(ull*)(ql_c + off) = pack4bf(l0, l1, l2, l3);
        bsplit(kv.x, h0, l0); bsplit(kv.y, h1, l1);
        bsplit(kv.z, h2, l2); bsplit(kv.w, h3, l3);
        *(ull*)(kh_c + off) = pack4bf(h0, h1, h2, h3);
        *(ull*)(kl_c + off) = pack4bf(l0, l1, l2, l3);
    }
    // prefill: sc[q][kk] = masked ? -1e30 : rel ; units = (qi,ki,qj), kj inner
    for (int uid = tid; uid < 343; uid += 128) {
        int qi = uid / 49, rem = uid - qi * 49;
        int ki = rem / 7,  qj = rem - ki * 7;
        bool m = masked && ((qi >= 4) != (ki >= 4));
        int q = qi * 7 + qj;
        const float* rp = &rel_s[(ki - qi + 6) * 13 + (6 - qj)];
        float* sp = &sc[q * SC + ki * 7];
#pragma unroll
        for (int kj = 0; kj < 7; kj++)
            sp[kj] = m ? -1e30f : rp[kj];
    }
    __syncthreads();

    // ---- scores via HMMA: warp w -> rows 16w..16w+15, cols 0..55 ----
    {
        const u32 qh_b = s2u(qh), ql_b = s2u(ql);
        const u32 kh_b = s2u(kh), kl_b = s2u(kl);
        const int lmat = lane >> 3;
        const int arow = warp * 16 + ((lmat & 1) ? 8 : 0) + (lane & 7);
        const int akc  = (lmat & 2) ? 8 : 0;
        const int brow = ((lmat & 2) ? 8 : 0) + (lane & 7);
        const int bkc  = (lmat & 1) ? 8 : 0;

        float c[7][4];
#pragma unroll
        for (int nt = 0; nt < 7; nt++)
#pragma unroll
            for (int j = 0; j < 4; j++) c[nt][j] = 0.f;

#pragma unroll
        for (int ks = 0; ks < 2; ks++) {
            const int kb = ks * 16;
            u32 aH[4], aL[4], bf[4][4];
            ldsm4(aH, sw_addr(qh_b, arow, kb + akc));
            ldsm4(aL, sw_addr(ql_b, arow, kb + akc));
#pragma unroll
            for (int p = 0; p < 4; p++)
                ldsm4(bf[p], sw_addr(kh_b, brow + p * 16, kb + bkc));
#pragma unroll
            for (int nt = 0; nt < 7; nt++)
                mma_bf16(c[nt], aH, bf[nt >> 1] + (nt & 1) * 2);
#pragma unroll
            for (int nt = 0; nt < 7; nt++)
                mma_bf16(c[nt], aL, bf[nt >> 1] + (nt & 1) * 2);
#pragma unroll
            for (int p = 0; p < 4; p++)
                ldsm4(bf[p], sw_addr(kl_b, brow + p * 16, kb + bkc));
#pragma unroll
            for (int nt = 0; nt < 7; nt++)
                mma_bf16(c[nt], aH, bf[nt >> 1] + (nt & 1) * 2);
        }

        // epilogue: sc += acc * scale (rel+mask already there); guard rows >= 49
        const float scale = 0.1767766952966369f;
        const int row0 = warp * 16 + (lane >> 2);
        const int colb = (lane & 3) * 2;
#pragma unroll
        for (int half = 0; half < 2; half++) {
            int r = row0 + half * 8;
            if (r < 49) {
                float* sp = &sc[r * SC + colb];
#pragma unroll
                for (int nt = 0; nt < 7; nt++) {
                    sp[nt * 8 + 0] += c[nt][half * 2 + 0] * scale;
                    sp[nt * 8 + 1] += c[nt][half * 2 + 1] * scale;
                }
            }
        }
    }
    __syncthreads();

    // ---- softmax per row ----
    for (int r = warp; r < 49; r += 4) {
        float v0 = sc[r * SC + lane];
        float v1 = (lane + 32 < 49) ? sc[r * SC + lane + 32] : -1e30f;
        float m = fmaxf(v0, v1);
#pragma unroll
        for (int off = 16; off > 0; off >>= 1)
            m = fmaxf(m, __shfl_xor_sync(0xffffffffu, m, off));
        float e0 = __expf(v0 - m);
        float e1 = (lane + 32 < 49) ? __expf(v1 - m) : 0.f;
        float s = e0 + e1;
#pragma unroll
        for (int off = 16; off > 0; off >>= 1)
            s += __shfl_xor_sync(0xffffffffu, s, off);
        float inv = 1.f / s;
        sc[r * SC + lane] = e0 * inv;
        if (lane + 32 < 49) sc[r * SC + lane + 32] = e1 * inv;
    }
    __syncthreads();

    // ---- P @ V : lane = d; warp handles q = warp + 4t ----
    const int d = lane;
    ull acc[13];
#pragma unroll
    for (int t = 0; t < 13; t++) acc[t] = 0ull;

#pragma unroll 1
    for (int it = 0; it < 12; it++) {
        int kk = it * 4;
        float v0 = vs[(kk + 0) * 36 + d];
        float v1 = vs[(kk + 1) * 36 + d];
        float v2 = vs[(kk + 2) * 36 + d];
        float v3 = vs[(kk + 3) * 36 + d];
        ull v01 = fpack(v0, v1), v23 = fpack(v2, v3);
#pragma unroll
        for (int t = 0; t < 13; t++) {
            int q = warp + 4 * t;
            if (q < 49) {
                ulonglong2 sp = *(const ulonglong2*)&sc[q * SC + kk];
                ffma2(acc[t], sp.x, v01);
                ffma2(acc[t], sp.y, v23);
            }
        }
    }
    float v48 = vs[48 * 36 + d];

#pragma unroll
    for (int t = 0; t < 13; t++) {
        int q = warp + 4 * t;
        if (q < 49) {
            float2 hv = funpack(acc[t]);
            float o = hv.x + hv.y + sc[q * SC + 48] * v48;
            size_t oidx = (size_t)(rowbase + q) * 384 + h * 32 + d;
            __nv_bfloat16 hh, ll;
            bsplit(o, hh, ll);
            oh[oidx] = hh;
            ol[oidx] = ll;
        }
    }
}

// ---------------- launch ----------------
extern "C" void kernel_launch(void* const* d_in, const int* in_sizes, int n_in,
                              void* d_out, int out_size)
{
    const float *x = nullptr, *wqkv = nullptr, *wout = nullptr,
                *bout = nullptr, *rel = nullptr;
    for (int i = 0; i < n_in; i++) {
        switch (in_sizes[i]) {
            case 19267584: x    = (const float*)d_in[i]; break;
            case 442368:   wqkv = (const float*)d_in[i]; break;
            case 147456:   wout = (const float*)d_in[i]; break;
            case 384:      bout = (const float*)d_in[i]; break;
            case 2028:     rel  = (const float*)d_in[i]; break;
        }
    }
    float* out = (float*)d_out;

    void *qkv_p, *xh_p, *xl_p, *ah_p, *al_p, *wqh_p, *wql_p, *woh_p, *wol_p;
    cudaGetSymbolAddress(&qkv_p, g_qkv);
    cudaGetSymbolAddress(&xh_p, g_xh);   cudaGetSymbolAddress(&xl_p, g_xl);
    cudaGetSymbolAddress(&ah_p, g_ah);   cudaGetSymbolAddress(&al_p, g_al);
    cudaGetSymbolAddress(&wqh_p, g_wqh); cudaGetSymbolAddress(&wql_p, g_wql);
    cudaGetSymbolAddress(&woh_p, g_woh); cudaGetSymbolAddress(&wol_p, g_wol);

    cudaFuncSetAttribute(gemm_mma<false, false>,
                         cudaFuncAttributeMaxDynamicSharedMemorySize, GEMM_SMEM);
    cudaFuncSetAttribute(gemm_mma<true, true>,
                         cudaFuncAttributeMaxDynamicSharedMemorySize, GEMM_SMEM);

    // 0) conversions
    conv_roll_kernel<<<(PIXN * 96 + 255) / 256, 256>>>(
        x, (__nv_bfloat16*)xh_p, (__nv_bfloat16*)xl_p);
    conv_wqkv_kernel<<<(110592 + 255) / 256, 256>>>(
        wqkv, (__nv_bfloat16*)wqh_p, (__nv_bfloat16*)wql_p);
    conv_plain_kernel<<<(36864 + 255) / 256, 256>>>(
        wout, (__nv_bfloat16*)woh_p, (__nv_bfloat16*)wol_p, 36864);

    // 1) qkv = roll(x) @ w_qkv^T   (window-major rows, head-major channels)
    {
        dim3 grid(1152 / 64, PIXN / 128);
        gemm_mma<false, false><<<grid, 128, GEMM_SMEM>>>(
            (const __nv_bfloat16*)xh_p, (const __nv_bfloat16*)xl_p,
            (const __nv_bfloat16*)wqh_p, (const __nv_bfloat16*)wql_p,
            nullptr, (float*)qkv_p, 1152);
    }
    // 2) windowed attention (HMMA scores) -> bf16 hi/lo (window-major rows)
    {
        dim3 grid(12, 64, 16);
        attn_kernel<<<grid, 128>>>(rel, (const float*)qkv_p,
                                   (__nv_bfloat16*)ah_p, (__nv_bfloat16*)al_p);
    }
    // 3) out = unwindow+unroll( att @ w_out^T + b_out )
    {
        dim3 grid(384 / 64, PIXN / 128);
        gemm_mma<true, true><<<grid, 128, GEMM_SMEM>>>(
            (const __nv_bfloat16*)ah_p, (const __nv_bfloat16*)al_p,
            (const __nv_bfloat16*)woh_p, (const __nv_bfloat16*)wol_p,
            bout, out, 384);
    }
}

// round 15
// speedup vs baseline: 1.4883x; 1.4883x over previous
#include <cuda_runtime.h>
#include <cuda_bf16.h>

typedef unsigned long long ull;
typedef unsigned int u32;

#define PIXN 50176
#define KDIM 384

// ---------------- scratch (static device allocations) ----------------
__device__ float g_qkv[57802752];                 // [PIXN][1152] f32, window-major rows, head-major channels
__device__ __nv_bfloat16 g_xh[19267584];          // x bf16 hi, window-major rows (rolled)
__device__ __nv_bfloat16 g_xl[19267584];
__device__ __nv_bfloat16 g_ah[19267584];          // attention out hi, window-major rows
__device__ __nv_bfloat16 g_al[19267584];
__device__ __nv_bfloat16 g_wqh[442368];           // w_qkv bf16 hi, rows permuted to h*96+mat*32+d
__device__ __nv_bfloat16 g_wql[442368];
__device__ __nv_bfloat16 g_woh[147456];
__device__ __nv_bfloat16 g_wol[147456];

// ---------------- helpers ----------------
__device__ __forceinline__ int roll3(int m) {
    int b = m / 3136; int p = m - b * 3136;
    int i = p / 56;   int j = p - i * 56;
    i += 3; if (i >= 56) i -= 56;
    j += 3; if (j >= 56) j -= 56;
    return b * 3136 + i * 56 + j;
}
// window-major index -> pixel index (same batch)
__device__ __forceinline__ int winpix(int m) {
    int b = m / 3136; int r = m - b * 3136;
    int win = r / 49;  int tok = r - win * 49;
    int wi = win >> 3, wj = win & 7;
    int ti = tok / 7,  tj = tok - ti * 7;
    return b * 3136 + (wi * 7 + ti) * 56 + wj * 7 + tj;
}

__device__ __forceinline__ ull fpack(float x, float y) {
    ull r; asm("mov.b64 %0, {%1, %2};" : "=l"(r) : "f"(x), "f"(y)); return r;
}
__device__ __forceinline__ void ffma2(ull &c, ull a, ull b) {
    asm("fma.rn.f32x2 %0, %1, %2, %0;" : "+l"(c) : "l"(a), "l"(b));
}
__device__ __forceinline__ float2 funpack(ull v) {
    float2 r; asm("mov.b64 {%0, %1}, %2;" : "=f"(r.x), "=f"(r.y) : "l"(v)); return r;
}
__device__ __forceinline__ u32 s2u(const void* p) {
    u32 a; asm("{ .reg .u64 t; cvta.to.shared.u64 t, %1; cvt.u32.u64 %0, t; }" : "=r"(a) : "l"(p));
    return a;
}
__device__ __forceinline__ void bsplit(float v, __nv_bfloat16& h, __nv_bfloat16& l) {
    h = __float2bfloat16(v);
    l = __float2bfloat16(v - __bfloat162float(h));
}
__device__ __forceinline__ void cp_async16(u32 d, const void* g) {
    asm volatile("cp.async.cg.shared.global [%0], [%1], 16;" :: "r"(d), "l"(g) : "memory");
}
__device__ __forceinline__ void ldsm4(u32* r, u32 addr) {
    asm volatile("ldmatrix.sync.aligned.m8n8.x4.shared.b16 {%0,%1,%2,%3}, [%4];"
                 : "=r"(r[0]), "=r"(r[1]), "=r"(r[2]), "=r"(r[3]) : "r"(addr));
}
__device__ __forceinline__ void mma_bf16(float* c, const u32* a, const u32* b) {
    asm volatile("mma.sync.aligned.m16n8k16.row.col.f32.bf16.bf16.f32 "
                 "{%0,%1,%2,%3},{%4,%5,%6,%7},{%8,%9},{%0,%1,%2,%3};"
                 : "+f"(c[0]), "+f"(c[1]), "+f"(c[2]), "+f"(c[3])
                 : "r"(a[0]), "r"(a[1]), "r"(a[2]), "r"(a[3]), "r"(b[0]), "r"(b[1]));
}

// ---------------- merged conversion kernel ----------------
// region 0: x -> window-major rolled bf16 hi/lo           (PIXN*96 float4 units)
// region 1: w_qkv (row-permuted) -> bf16 hi/lo            (110592 units)
// region 2: w_out -> bf16 hi/lo                           (36864 units)
#define CONV_N0 (PIXN * 96)
#define CONV_N1 110592
#define CONV_N2 36864
#define CONV_TOTAL (CONV_N0 + CONV_N1 + CONV_N2)

__global__ void conv_all_kernel(const float* __restrict__ x,
                                const float* __restrict__ wqkv,
                                const float* __restrict__ wout,
                                __nv_bfloat16* __restrict__ xh, __nv_bfloat16* __restrict__ xl,
                                __nv_bfloat16* __restrict__ wqh, __nv_bfloat16* __restrict__ wql,
                                __nv_bfloat16* __restrict__ woh, __nv_bfloat16* __restrict__ wol)
{
    int idx = blockIdx.x * 256 + threadIdx.x;
    if (idx >= CONV_TOTAL) return;

    const float4* src4;
    __nv_bfloat162 *hp, *lp;
    if (idx < CONV_N0) {
        int m = idx / 96, j = idx - m * 96;
        int src = roll3(winpix(m));
        src4 = (const float4*)x + (size_t)src * 96 + j;
        hp = (__nv_bfloat162*)(xh + (size_t)m * 384 + j * 4);
        lp = (__nv_bfloat162*)(xl + (size_t)m * 384 + j * 4);
    } else if (idx < CONV_N0 + CONV_N1) {
        int t = idx - CONV_N0;
        int drow = t / 96, j = t - drow * 96;
        int h = drow / 96, rem = drow - h * 96;
        int mat = rem >> 5, d = rem & 31;
        int srow = mat * 384 + h * 32 + d;
        src4 = (const float4*)wqkv + (size_t)srow * 96 + j;
        hp = (__nv_bfloat162*)(wqh + (size_t)drow * 384 + j * 4);
        lp = (__nv_bfloat162*)(wql + (size_t)drow * 384 + j * 4);
    } else {
        int t = idx - CONV_N0 - CONV_N1;
        src4 = (const float4*)wout + t;
        hp = (__nv_bfloat162*)(woh + (size_t)t * 4);
        lp = (__nv_bfloat162*)(wol + (size_t)t * 4);
    }

    float4 v = *src4;
    __nv_bfloat16 h0, h1, h2, h3, l0, l1, l2, l3;
    bsplit(v.x, h0, l0); bsplit(v.y, h1, l1); bsplit(v.z, h2, l2); bsplit(v.w, h3, l3);
    hp[0] = __nv_bfloat162{h0, h1}; hp[1] = __nv_bfloat162{h2, h3};
    lp[0] = __nv_bfloat162{l0, l1}; lp[1] = __nv_bfloat162{l2, l3};
}

// ---------------- warp-MMA split-bf16 GEMM (R12/R13 structure, committed) ----------------
#define MATB_A 8192            // 128 rows * 64B
#define MATB_B 4096            // 64 rows * 64B
#define STAGE  24576           // Ah, Al, Bh, Bl
#define NSTG   3
#define GEMM_SMEM (NSTG * STAGE)
#define NCHUNK 12

__device__ __forceinline__ u32 sw_addr(u32 base, int row, int kc) {
    return base + row * 64 + ((((u32)kc >> 3) ^ (((u32)row >> 1) & 3)) << 4);
}

template<bool BIAS, bool ROLLOUT>
__global__ __launch_bounds__(128, 3)
void gemm_mma(const __nv_bfloat16* __restrict__ Ah, const __nv_bfloat16* __restrict__ Al,
              const __nv_bfloat16* __restrict__ Bh, const __nv_bfloat16* __restrict__ Bl,
              const float* __restrict__ bias, float* __restrict__ C, int N)
{
    extern __shared__ char smem[];
    const int tid = threadIdx.x;
    const int wid = tid >> 5, lane = tid & 31;
    const int mBase = blockIdx.y * 128, nBase = blockIdx.x * 64;
    const int wm = wid;

    const u32 s0 = s2u(smem);
    const char* Ahc = (const char*)Ah;
    const char* Alc = (const char*)Al;
    const char* Bhc = (const char*)Bh;
    const char* Blc = (const char*)Bl;

    float c[2][8][4];
#pragma unroll
    for (int i = 0; i < 2; i++)
#pragma unroll
        for (int j = 0; j < 8; j++)
#pragma unroll
            for (int k = 0; k < 4; k++) c[i][j][k] = 0.f;

    const int lmat = lane >> 3;
    const int arow0 = wm * 32 + ((lmat & 1) ? 8 : 0) + (lane & 7);
    const int akc0  = (lmat & 2) ? 8 : 0;
    const int brow0 = ((lmat & 2) ? 8 : 0) + (lane & 7);
    const int bkc0  = (lmat & 1) ? 8 : 0;

    auto load_chunk = [&](int ck, int st) {
        u32 sbase = s0 + st * STAGE;
#pragma unroll
        for (int v = 0; v < 12; v++) {
            int idx = v * 128 + tid;          // 0..1535
            const char* g;
            u32 dst;
            if (idx < 1024) {
                int mat = idx >> 9;
                int r   = (idx >> 2) & 127;
                int cc  = idx & 3;
                const char* gb = (mat == 0) ? Ahc : Alc;
                g = gb + (size_t)(mBase + r) * 768 + ck * 64 + cc * 16;
                u32 swg = (u32)cc ^ (((u32)r >> 1) & 3);
                dst = sbase + mat * MATB_A + r * 64 + swg * 16;
            } else {
                int j   = idx - 1024;
                int mat = j >> 8;
                int r   = (j >> 2) & 63;
                int cc  = j & 3;
                const char* gb = (mat == 0) ? Bhc : Blc;
                g = gb + (size_t)(nBase + r) * 768 + ck * 64 + cc * 16;
                u32 swg = (u32)cc ^ (((u32)r >> 1) & 3);
                dst = sbase + 2 * MATB_A + mat * MATB_B + r * 64 + swg * 16;
            }
            cp_async16(dst, g);
        }
        asm volatile("cp.async.commit_group;" ::: "memory");
    };

    auto compute = [&](int st) {
        u32 sbase = s0 + st * STAGE;
        const u32 bhb = sbase + 2 * MATB_A;
        const u32 blb = bhb + MATB_B;
#pragma unroll
        for (int ks = 0; ks < 2; ks++) {
            const int kb = ks * 16;
            u32 ah[2][4], al[2][4], bh[4][4];
            ldsm4(ah[0], sw_addr(sbase,          arow0,      kb + akc0));
            ldsm4(ah[1], sw_addr(sbase,          arow0 + 16, kb + akc0));
            ldsm4(al[0], sw_addr(sbase + MATB_A, arow0,      kb + akc0));
            ldsm4(al[1], sw_addr(sbase + MATB_A, arow0 + 16, kb + akc0));
#pragma unroll
            for (int p = 0; p < 4; p++)
                ldsm4(bh[p], sw_addr(bhb, brow0 + p * 16, kb + bkc0));
#pragma unroll
            for (int p = 0; p < 4; p++) {
                mma_bf16(c[0][2 * p],     ah[0], bh[p]);
                mma_bf16(c[1][2 * p],     ah[1], bh[p]);
                mma_bf16(c[0][2 * p + 1], ah[0], bh[p] + 2);
                mma_bf16(c[1][2 * p + 1], ah[1], bh[p] + 2);
            }
#pragma unroll
            for (int p = 0; p < 4; p++) {
                mma_bf16(c[0][2 * p],     al[0], bh[p]);
                mma_bf16(c[1][2 * p],     al[1], bh[p]);
                mma_bf16(c[0][2 * p + 1], al[0], bh[p] + 2);
                mma_bf16(c[1][2 * p + 1], al[1], bh[p] + 2);
            }
#pragma unroll
            for (int p = 0; p < 4; p++) {
                u32 u[4];
                ldsm4(u, sw_addr(blb, brow0 + p * 16, kb + bkc0));
                mma_bf16(c[0][2 * p],     ah[0], u);
                mma_bf16(c[1][2 * p],     ah[1], u);
                mma_bf16(c[0][2 * p + 1], ah[0], u + 2);
                mma_bf16(c[1][2 * p + 1], ah[1], u + 2);
            }
        }
    };

    load_chunk(0, 0);
    load_chunk(1, 1);
    int st = 0, pst = 2;
#pragma unroll 1
    for (int ck = 0; ck < NCHUNK; ck++) {
        if (ck < NCHUNK - 1)
            asm volatile("cp.async.wait_group 1;" ::: "memory");
        else
            asm volatile("cp.async.wait_group 0;" ::: "memory");
        __syncthreads();
        if (ck < NCHUNK - 2) load_chunk(ck + 2, pst);
        compute(st);
        st = (st == NSTG - 1) ? 0 : st + 1;
        pst = (pst == NSTG - 1) ? 0 : pst + 1;
    }

#pragma unroll
    for (int mt = 0; mt < 2; mt++) {
#pragma unroll
        for (int half = 0; half < 2; half++) {
            int row = mBase + wm * 32 + mt * 16 + (lane >> 2) + half * 8;
            if (ROLLOUT) row = roll3(winpix(row));   // window-major -> unrolled pixel
            float* cp = C + (size_t)row * N + nBase + (lane & 3) * 2;
#pragma unroll
            for (int nt = 0; nt < 8; nt++) {
                float2 v;
                v.x = c[mt][nt][half * 2 + 0];
                v.y = c[mt][nt][half * 2 + 1];
                if (BIAS) {
                    int col = nBase + nt * 8 + (lane & 3) * 2;
                    v.x += bias[col]; v.y += bias[col + 1];
                }
                *(float2*)(cp + nt * 8) = v;
            }
        }
    }
}

// ---------------- windowed attention (R13 version, proven best) ----------------
#define SC 52

__global__ __launch_bounds__(128)
void attn_kernel(const float* __restrict__ rel, const float* __restrict__ qkv,
                 __nv_bfloat16* __restrict__ oh, __nv_bfloat16* __restrict__ ol)
{
    const int h   = blockIdx.x;
    const int win = blockIdx.y;
    const int b   = blockIdx.z;
    const int tid = threadIdx.x;
    const int warp = tid >> 5, lane = tid & 31;

    __shared__ float qs[49 * 36];
    __shared__ float ks[49 * 36];
    __shared__ float vs[49 * 36];
    __shared__ float sc[49 * SC];
    __shared__ float rel_s[169];

    const bool masked = (win >= 56);   // wi == 7

    for (int i = tid; i < 169; i += 128) rel_s[i] = rel[i * 12 + h];

    // streaming gather: token rows contiguous, q/k/v contiguous per token
    const int rowbase = b * 3136 + win * 49;
    const float* pb = qkv + (size_t)rowbase * 1152 + h * 96;
    for (int idx = tid; idx < 49 * 8; idx += 128) {
        int tok = idx >> 3, d4 = idx & 7;
        const float* p = pb + (size_t)tok * 1152 + d4 * 4;
        *(float4*)&qs[tok * 36 + d4 * 4] = *(const float4*)(p);
        *(float4*)&ks[tok * 36 + d4 * 4] = *(const float4*)(p + 32);
        *(float4*)&vs[tok * 36 + d4 * 4] = *(const float4*)(p + 64);
    }
    __syncthreads();

    // scores: lanes = q; warps split (q-half, kk-half)
    {
        int q = (warp & 1) * 32 + lane;
        int kk0 = (warp >> 1) ? 25 : 0;
        int kk1 = (warp >> 1) ? 49 : 25;
        if (q < 49) {
            ull qp[16];
            const ulonglong2* qrow = (const ulonglong2*)&qs[q * 36];
#pragma unroll
            for (int i = 0; i < 8; i++) {
                ulonglong2 t = qrow[i];
                qp[2 * i] = t.x; qp[2 * i + 1] = t.y;
            }
            int qi = q / 7, qj = q - qi * 7;
            int ki = kk0 / 7, kj = kk0 - ki * 7;
            const float scale = 0.1767766952966369f;
            for (int kk = kk0; kk < kk1; kk++) {
                const ulonglong2* krow = (const ulonglong2*)&ks[kk * 36];
                ull a0 = 0, a1 = 0, a2 = 0, a3 = 0;
#pragma unroll
                for (int i = 0; i < 4; i++) {
                    ulonglong2 ta = krow[2 * i];
                    ulonglong2 tb = krow[2 * i + 1];
                    ffma2(a0, qp[4 * i + 0], ta.x);
                    ffma2(a1, qp[4 * i + 1], ta.y);
                    ffma2(a2, qp[4 * i + 2], tb.x);
                    ffma2(a3, qp[4 * i + 3], tb.y);
                }
                float2 h0 = funpack(a0), h1 = funpack(a1);
                float2 h2 = funpack(a2), h3 = funpack(a3);
                float dot = (h0.x + h0.y) + (h1.x + h1.y) + (h2.x + h2.y) + (h3.x + h3.y);
                float s = dot * scale + rel_s[(ki - qi + 6) * 13 + (kj - qj + 6)];
                if (masked && ((q >= 28) != (kk >= 28))) s = -1e30f;
                sc[q * SC + kk] = s;
                kj++; if (kj == 7) { kj = 0; ki++; }
            }
        }
    }
    __syncthreads();

    // softmax per row
    for (int r = warp; r < 49; r += 4) {
        float v0 = sc[r * SC + lane];
        float v1 = (lane + 32 < 49) ? sc[r * SC + lane + 32] : -1e30f;
        float m = fmaxf(v0, v1);
#pragma unroll
        for (int off = 16; off > 0; off >>= 1)
            m = fmaxf(m, __shfl_xor_sync(0xffffffffu, m, off));
        float e0 = __expf(v0 - m);
        float e1 = (lane + 32 < 49) ? __expf(v1 - m) : 0.f;
        float s = e0 + e1;
#pragma unroll
        for (int off = 16; off > 0; off >>= 1)
            s += __shfl_xor_sync(0xffffffffu, s, off);
        float inv = 1.f / s;
        sc[r * SC + lane] = e0 * inv;
        if (lane + 32 < 49) sc[r * SC + lane + 32] = e1 * inv;
    }
    __syncthreads();

    // P @ V
    const int d = lane;
    ull acc[13];
#pragma unroll
    for (int t = 0; t < 13; t++) acc[t] = 0ull;

#pragma unroll 1
    for (int it = 0; it < 12; it++) {
        int kk = it * 4;
        float v0 = vs[(kk + 0) * 36 + d];
        float v1 = vs[(kk + 1) * 36 + d];
        float v2 = vs[(kk + 2) * 36 + d];
        float v3 = vs[(kk + 3) * 36 + d];
        ull v01 = fpack(v0, v1), v23 = fpack(v2, v3);
#pragma unroll
        for (int t = 0; t < 13; t++) {
            int q = warp + 4 * t;
            if (q < 49) {
                ulonglong2 sp = *(const ulonglong2*)&sc[q * SC + kk];
                ffma2(acc[t], sp.x, v01);
                ffma2(acc[t], sp.y, v23);
            }
        }
    }
    float v48 = vs[48 * 36 + d];

#pragma unroll
    for (int t = 0; t < 13; t++) {
        int q = warp + 4 * t;
        if (q < 49) {
            float2 hv = funpack(acc[t]);
            float o = hv.x + hv.y + sc[q * SC + 48] * v48;
            size_t oidx = (size_t)(rowbase + q) * 384 + h * 32 + d;
            __nv_bfloat16 hh, ll;
            bsplit(o, hh, ll);
            oh[oidx] = hh;
            ol[oidx] = ll;
        }
    }
}

// ---------------- launch ----------------
extern "C" void kernel_launch(void* const* d_in, const int* in_sizes, int n_in,
                              void* d_out, int out_size)
{
    const float *x = nullptr, *wqkv = nullptr, *wout = nullptr,
                *bout = nullptr, *rel = nullptr;
    for (int i = 0; i < n_in; i++) {
        switch (in_sizes[i]) {
            case 19267584: x    = (const float*)d_in[i]; break;
            case 442368:   wqkv = (const float*)d_in[i]; break;
            case 147456:   wout = (const float*)d_in[i]; break;
            case 384:      bout = (const float*)d_in[i]; break;
            case 2028:     rel  = (const float*)d_in[i]; break;
        }
    }
    float* out = (float*)d_out;

    void *qkv_p, *xh_p, *xl_p, *ah_p, *al_p, *wqh_p, *wql_p, *woh_p, *wol_p;
    cudaGetSymbolAddress(&qkv_p, g_qkv);
    cudaGetSymbolAddress(&xh_p, g_xh);   cudaGetSymbolAddress(&xl_p, g_xl);
    cudaGetSymbolAddress(&ah_p, g_ah);   cudaGetSymbolAddress(&al_p, g_al);
    cudaGetSymbolAddress(&wqh_p, g_wqh); cudaGetSymbolAddress(&wql_p, g_wql);
    cudaGetSymbolAddress(&woh_p, g_woh); cudaGetSymbolAddress(&wol_p, g_wol);

    cudaFuncSetAttribute(gemm_mma<false, false>,
                         cudaFuncAttributeMaxDynamicSharedMemorySize, GEMM_SMEM);
    cudaFuncSetAttribute(gemm_mma<true, true>,
                         cudaFuncAttributeMaxDynamicSharedMemorySize, GEMM_SMEM);

    // 0) merged conversions
    conv_all_kernel<<<(CONV_TOTAL + 255) / 256, 256>>>(
        x, wqkv, wout,
        (__nv_bfloat16*)xh_p, (__nv_bfloat16*)xl_p,
        (__nv_bfloat16*)wqh_p, (__nv_bfloat16*)wql_p,
        (__nv_bfloat16*)woh_p, (__nv_bfloat16*)wol_p);

    // 1) qkv = roll(x) @ w_qkv^T   (window-major rows, head-major channels)
    {
        dim3 grid(1152 / 64, PIXN / 128);
        gemm_mma<false, false><<<grid, 128, GEMM_SMEM>>>(
            (const __nv_bfloat16*)xh_p, (const __nv_bfloat16*)xl_p,
            (const __nv_bfloat16*)wqh_p, (const __nv_bfloat16*)wql_p,
            nullptr, (float*)qkv_p, 1152);
    }
    // 2) windowed attention -> bf16 hi/lo (window-major rows)
    {
        dim3 grid(12, 64, 16);
        attn_kernel<<<grid, 128>>>(rel, (const float*)qkv_p,
                                   (__nv_bfloat16*)ah_p, (__nv_bfloat16*)al_p);
    }
    // 3) out = unwindow+unroll( att @ w_out^T + b_out )
    {
        dim3 grid(384 / 64, PIXN / 128);
        gemm_mma<true, true><<<grid, 128, GEMM_SMEM>>>(
            (const __nv_bfloat16*)ah_p, (const __nv_bfloat16*)al_p,
            (const __nv_bfloat16*)woh_p, (const __nv_bfloat16*)wol_p,
            bout, out, 384);
    }
}